// round 2
// baseline (speedup 1.0000x reference)
#include <cuda_runtime.h>
#include <cuda_bf16.h>

#define NMAX 100000
#define EMAX 3200000
#define K_IN 116
#define H_OUT 256
#define TILE_R 64

// Scratch (static device globals: allocation-free per harness rules)
__device__ int   g_deg[NMAX];
__device__ int   g_cursor[NMAX];
__device__ float g_dinv[NMAX];
__device__ int   g_rowptr[NMAX + 1];
__device__ int   g_col[EMAX];
__device__ float g_agg[(size_t)NMAX * K_IN];

// ---------------------------------------------------------------------------
// 0) zero degree + cursor
__global__ void zero_kernel(int n) {
    int i = blockIdx.x * blockDim.x + threadIdx.x;
    if (i < n) { g_deg[i] = 0; g_cursor[i] = 0; }
}

// 1) count in-degrees (dst side of edge list)
__global__ void count_kernel(const int* __restrict__ dst, int e) {
    int i = blockIdx.x * blockDim.x + threadIdx.x;
    if (i < e) atomicAdd(&g_deg[dst[i]], 1);
}

// 2) dinv = rsqrt(deg + 1)   (+1 for the self-loop; always > 0)
__global__ void dinv_kernel(int n) {
    int i = blockIdx.x * blockDim.x + threadIdx.x;
    if (i < n) g_dinv[i] = rsqrtf((float)(g_deg[i] + 1));
}

// 3) exclusive prefix sum of g_deg -> g_rowptr  (single block, 1024 threads)
__global__ void scan_kernel(int n) {
    __shared__ int s[1024];
    int tid = threadIdx.x;
    int chunk = (n + 1023) >> 10;
    int lo = tid * chunk;
    int hi = min(lo + chunk, n);
    if (hi < lo) hi = lo;
    int sum = 0;
    for (int i = lo; i < hi; i++) sum += g_deg[i];
    s[tid] = sum;
    __syncthreads();
    // Kogge-Stone inclusive scan
    for (int off = 1; off < 1024; off <<= 1) {
        int v = 0;
        if (tid >= off) v = s[tid - off];
        __syncthreads();
        s[tid] += v;
        __syncthreads();
    }
    int run = (tid == 0) ? 0 : s[tid - 1];
    for (int i = lo; i < hi; i++) { g_rowptr[i] = run; run += g_deg[i]; }
    if (tid == 0) g_rowptr[n] = s[1023];
}

// 4) bucket fill: scatter src ids into per-dst CSR lists
__global__ void fill_kernel(const int* __restrict__ src,
                            const int* __restrict__ dst, int e) {
    int i = blockIdx.x * blockDim.x + threadIdx.x;
    if (i < e) {
        int d = dst[i];
        int p = g_rowptr[d] + atomicAdd(&g_cursor[d], 1);
        g_col[p] = src[i];
    }
}

// 5) pull aggregation: one warp per destination node.
//    agg[dst] = dinv[dst]^2 * x[dst] + sum_{src in N(dst)} dinv[src]*dinv[dst]*x[src]
__global__ void agg_kernel(const float* __restrict__ x, int n) {
    int gwarp = (blockIdx.x * blockDim.x + threadIdx.x) >> 5;
    int lane  = threadIdx.x & 31;
    if (gwarp >= n) return;
    int dst = gwarp;
    float di = g_dinv[dst];
    bool active = lane < (K_IN / 4);   // 29 lanes * float4 = 116

    float4 acc = make_float4(0.f, 0.f, 0.f, 0.f);
    if (active) {
        float4 v = ((const float4*)(x + (size_t)dst * K_IN))[lane];
        float w = di * di;   // self-loop
        acc.x = v.x * w; acc.y = v.y * w; acc.z = v.z * w; acc.w = v.w * w;
    }
    int beg = g_rowptr[dst];
    int end = g_rowptr[dst + 1];
    for (int e = beg; e < end; e++) {
        int s = g_col[e];             // broadcast (same addr all lanes)
        float w = g_dinv[s] * di;     // broadcast
        if (active) {
            float4 v = ((const float4*)(x + (size_t)s * K_IN))[lane];
            acc.x += v.x * w; acc.y += v.y * w; acc.z += v.z * w; acc.w += v.w * w;
        }
    }
    if (active)
        ((float4*)(g_agg + (size_t)dst * K_IN))[lane] = acc;
}

// 6) GEMM: out = relu(agg @ W + b)
//    Whole W (116x256, 118KB) + 64-row agg tile (29KB) in dynamic SMEM.
//    256 threads; thread = (rowgroup tid>>6 of 16 rows) x (colgroup tid&63 of 4 cols).
__global__ __launch_bounds__(256) void gemm_kernel(const float* __restrict__ W,
                                                   const float* __restrict__ b,
                                                   float* __restrict__ out, int n) {
    extern __shared__ float sh[];
    float* Ws = sh;                    // K_IN * H_OUT
    float* Xs = sh + K_IN * H_OUT;     // TILE_R * K_IN
    int tid = threadIdx.x;

    // cooperative load of W (float4)
    {
        const float4* Wg = (const float4*)W;
        float4* Ws4 = (float4*)Ws;
        #pragma unroll 4
        for (int i = tid; i < (K_IN * H_OUT) / 4; i += 256) Ws4[i] = Wg[i];
    }
    int row0 = blockIdx.x * TILE_R;
    int nrows = n - row0; if (nrows > TILE_R) nrows = TILE_R;
    {
        const float4* Ag = (const float4*)(g_agg + (size_t)row0 * K_IN);
        float4* Xs4 = (float4*)Xs;
        int tot4 = nrows * (K_IN / 4);
        for (int i = tid; i < tot4; i += 256) Xs4[i] = Ag[i];
    }
    __syncthreads();

    int cbase = (tid & 63) * 4;
    int rbase = (tid >> 6) * 16;

    float4 acc[16];
    #pragma unroll
    for (int r = 0; r < 16; r++) acc[r] = make_float4(0.f, 0.f, 0.f, 0.f);

    #pragma unroll 4
    for (int k = 0; k < K_IN; k++) {
        float4 wv = *(const float4*)&Ws[k * H_OUT + cbase];
        #pragma unroll
        for (int r = 0; r < 16; r++) {
            float xv = Xs[(rbase + r) * K_IN + k];   // warp broadcast
            acc[r].x += xv * wv.x;
            acc[r].y += xv * wv.y;
            acc[r].z += xv * wv.z;
            acc[r].w += xv * wv.w;
        }
    }

    float4 bv = *(const float4*)&b[cbase];
    #pragma unroll
    for (int r = 0; r < 16; r++) {
        int row = row0 + rbase + r;
        if (row < n) {
            float4 o;
            o.x = fmaxf(acc[r].x + bv.x, 0.f);
            o.y = fmaxf(acc[r].y + bv.y, 0.f);
            o.z = fmaxf(acc[r].z + bv.z, 0.f);
            o.w = fmaxf(acc[r].w + bv.w, 0.f);
            *(float4*)&out[(size_t)row * H_OUT + cbase] = o;
        }
    }
}

// ---------------------------------------------------------------------------
extern "C" void kernel_launch(void* const* d_in, const int* in_sizes, int n_in,
                              void* d_out, int out_size) {
    const float* x  = (const float*)d_in[0];
    const int*   ei = (const int*)d_in[1];
    const float* W  = (const float*)d_in[2];
    const float* b  = (const float*)d_in[3];
    float* out = (float*)d_out;

    int n = in_sizes[0] / K_IN;     // 100000
    int e = in_sizes[1] / 2;        // 3200000
    const int* src = ei;
    const int* dst = ei + e;

    int nb_n = (n + 255) / 256;
    int nb_e = (e + 255) / 256;

    zero_kernel<<<nb_n, 256>>>(n);
    count_kernel<<<nb_e, 256>>>(dst, e);
    dinv_kernel<<<nb_n, 256>>>(n);
    scan_kernel<<<1, 1024>>>(n);
    fill_kernel<<<nb_e, 256>>>(src, dst, e);

    int warps = n;
    int nb_agg = (warps * 32 + 255) / 256;
    agg_kernel<<<nb_agg, 256>>>(x, n);

    int smem = (K_IN * H_OUT + TILE_R * K_IN) * sizeof(float);  // 148480 B
    cudaFuncSetAttribute(gemm_kernel, cudaFuncAttributeMaxDynamicSharedMemorySize, smem);
    int nb_gemm = (n + TILE_R - 1) / TILE_R;
    gemm_kernel<<<nb_gemm, 256, smem>>>(W, b, out, n);
}

// round 3
// speedup vs baseline: 1.2099x; 1.2099x over previous
#include <cuda_runtime.h>
#include <cuda_bf16.h>

#define NMAX 100000
#define EMAX 3200000
#define K_IN 116
#define K2   (K_IN / 2)      // 58 k-pairs
#define H_OUT 256
#define TILE_R 64
#define SCAN_B 256           // elements per scan block

// Scratch (static device globals: allocation-free per harness rules)
__device__ int   g_deg[NMAX];
__device__ int   g_cursor[NMAX];
__device__ float g_dinv[NMAX];
__device__ int   g_rowptr[NMAX + 1];
__device__ int   g_col[EMAX];
__device__ float g_agg[(size_t)NMAX * K_IN];
__device__ int   g_bsum[(NMAX + SCAN_B - 1) / SCAN_B];
__device__ int   g_boff[(NMAX + SCAN_B - 1) / SCAN_B];

// ---------------------------------------------------------------------------
__global__ void zero_kernel(int n) {
    int i = blockIdx.x * blockDim.x + threadIdx.x;
    if (i < n) { g_deg[i] = 0; g_cursor[i] = 0; }
}

__global__ void count_kernel(const int* __restrict__ dst, int e) {
    int i = blockIdx.x * blockDim.x + threadIdx.x;
    if (i < e) atomicAdd(&g_deg[dst[i]], 1);
}

__global__ void dinv_kernel(int n) {
    int i = blockIdx.x * blockDim.x + threadIdx.x;
    if (i < n) g_dinv[i] = rsqrtf((float)(g_deg[i] + 1));
}

// --- 3-phase scan ---------------------------------------------------------
// A) per-block partial sums of g_deg
__global__ void scanA_kernel(int n) {
    __shared__ int s[SCAN_B];
    int g = blockIdx.x * SCAN_B + threadIdx.x;
    int v = (g < n) ? g_deg[g] : 0;
    s[threadIdx.x] = v;
    __syncthreads();
    for (int off = SCAN_B / 2; off > 0; off >>= 1) {
        if (threadIdx.x < off) s[threadIdx.x] += s[threadIdx.x + off];
        __syncthreads();
    }
    if (threadIdx.x == 0) g_bsum[blockIdx.x] = s[0];
}

// B) single-block exclusive scan of the 391 partials
__global__ void scanB_kernel(int nb) {
    __shared__ int s[512];
    int tid = threadIdx.x;
    int v = (tid < nb) ? g_bsum[tid] : 0;
    s[tid] = v;
    __syncthreads();
    for (int off = 1; off < 512; off <<= 1) {
        int t = (tid >= off) ? s[tid - off] : 0;
        __syncthreads();
        s[tid] += t;
        __syncthreads();
    }
    if (tid < nb) g_boff[tid] = s[tid] - v;   // exclusive
}

// C) per-block exclusive scan + offset -> rowptr
__global__ void scanC_kernel(int n) {
    __shared__ int s[SCAN_B];
    int tid = threadIdx.x;
    int g = blockIdx.x * SCAN_B + tid;
    int d = (g < n) ? g_deg[g] : 0;
    s[tid] = d;
    __syncthreads();
    for (int off = 1; off < SCAN_B; off <<= 1) {
        int t = (tid >= off) ? s[tid - off] : 0;
        __syncthreads();
        s[tid] += t;
        __syncthreads();
    }
    int incl = s[tid];
    int base = g_boff[blockIdx.x];
    if (g < n)      g_rowptr[g] = base + incl - d;
    if (g == n - 1) g_rowptr[n] = base + incl;
}

// --- bucket fill ----------------------------------------------------------
__global__ void fill_kernel(const int* __restrict__ src,
                            const int* __restrict__ dst, int e) {
    int i = blockIdx.x * blockDim.x + threadIdx.x;
    if (i < e) {
        int d = dst[i];
        int p = g_rowptr[d] + atomicAdd(&g_cursor[d], 1);
        g_col[p] = src[i];
    }
}

// --- pull aggregation: one warp per destination node ----------------------
__global__ void agg_kernel(const float* __restrict__ x, int n) {
    int gwarp = (blockIdx.x * blockDim.x + threadIdx.x) >> 5;
    int lane  = threadIdx.x & 31;
    if (gwarp >= n) return;
    int dst = gwarp;
    float di = g_dinv[dst];
    bool active = lane < (K_IN / 4);   // 29 lanes * float4 = 116

    float4 acc = make_float4(0.f, 0.f, 0.f, 0.f);
    if (active) {
        float4 v = ((const float4*)(x + (size_t)dst * K_IN))[lane];
        float w = di * di;   // self-loop
        acc.x = v.x * w; acc.y = v.y * w; acc.z = v.z * w; acc.w = v.w * w;
    }
    int e   = g_rowptr[dst];
    int end = g_rowptr[dst + 1];
    // 4x unrolled edge loop for MLP on the L2-resident x-row gathers
    for (; e + 4 <= end; e += 4) {
        int s0 = g_col[e], s1 = g_col[e+1], s2 = g_col[e+2], s3 = g_col[e+3];
        float w0 = g_dinv[s0] * di, w1 = g_dinv[s1] * di;
        float w2 = g_dinv[s2] * di, w3 = g_dinv[s3] * di;
        if (active) {
            float4 v0 = ((const float4*)(x + (size_t)s0 * K_IN))[lane];
            float4 v1 = ((const float4*)(x + (size_t)s1 * K_IN))[lane];
            float4 v2 = ((const float4*)(x + (size_t)s2 * K_IN))[lane];
            float4 v3 = ((const float4*)(x + (size_t)s3 * K_IN))[lane];
            acc.x += v0.x*w0; acc.y += v0.y*w0; acc.z += v0.z*w0; acc.w += v0.w*w0;
            acc.x += v1.x*w1; acc.y += v1.y*w1; acc.z += v1.z*w1; acc.w += v1.w*w1;
            acc.x += v2.x*w2; acc.y += v2.y*w2; acc.z += v2.z*w2; acc.w += v2.w*w2;
            acc.x += v3.x*w3; acc.y += v3.y*w3; acc.z += v3.z*w3; acc.w += v3.w*w3;
        }
    }
    for (; e < end; e++) {
        int s = g_col[e];
        float w = g_dinv[s] * di;
        if (active) {
            float4 v = ((const float4*)(x + (size_t)s * K_IN))[lane];
            acc.x += v.x*w; acc.y += v.y*w; acc.z += v.z*w; acc.w += v.w*w;
        }
    }
    if (active)
        ((float4*)(g_agg + (size_t)dst * K_IN))[lane] = acc;
}

// --- GEMM: out = relu(agg @ W + b), packed f32x2 FMA ----------------------
// SMEM: Wp = W interleaved as k-pairs: float2 Wp[k2][c] = {W[2k2][c], W[2k2+1][c]}
//       Xs = 64-row agg tile, row-major  (LDS.64 gives {X[r][2k2],X[r][2k2+1]} free)
// Each thread: 16 rows x 4 cols; accumulator = f32x2 per (r,c): {even-k sum, odd-k sum}
__global__ __launch_bounds__(256) void gemm_kernel(const float* __restrict__ W,
                                                   const float* __restrict__ b,
                                                   float* __restrict__ out, int n) {
    extern __shared__ float sh[];
    float* Wp = sh;                    // K_IN * H_OUT floats (k-pair interleaved)
    float* Xs = sh + K_IN * H_OUT;     // TILE_R * K_IN
    int tid = threadIdx.x;

    // cooperative load+interleave of W
    for (int i = tid; i < (K_IN * H_OUT) / 4; i += 256) {
        int k = i >> 6;            // / 64
        int c = (i & 63) * 4;
        float4 wv = ((const float4*)W)[i];
        int base = ((k >> 1) * H_OUT + c) * 2 + (k & 1);
        Wp[base + 0] = wv.x;
        Wp[base + 2] = wv.y;
        Wp[base + 4] = wv.z;
        Wp[base + 6] = wv.w;
    }
    int row0 = blockIdx.x * TILE_R;
    int nrows = n - row0; if (nrows > TILE_R) nrows = TILE_R;
    {
        const float4* Ag = (const float4*)(g_agg + (size_t)row0 * K_IN);
        float4* Xs4 = (float4*)Xs;
        int tot4 = nrows * (K_IN / 4);
        for (int i = tid; i < tot4; i += 256) Xs4[i] = Ag[i];
    }
    __syncthreads();

    int cbase = (tid & 63) * 4;
    int rbase = (tid >> 6) * 16;

    unsigned long long acc[16][4];
    #pragma unroll
    for (int r = 0; r < 16; r++)
        #pragma unroll
        for (int c = 0; c < 4; c++) acc[r][c] = 0ull;

    #pragma unroll 2
    for (int k2 = 0; k2 < K2; k2++) {
        // 8 contiguous floats = 4 f32x2 pairs for cols cbase..cbase+3
        const float* wrow = &Wp[(k2 * H_OUT + cbase) * 2];
        unsigned long long w0 = *(const unsigned long long*)(wrow + 0);
        unsigned long long w1 = *(const unsigned long long*)(wrow + 2);
        unsigned long long w2 = *(const unsigned long long*)(wrow + 4);
        unsigned long long w3 = *(const unsigned long long*)(wrow + 6);
        #pragma unroll
        for (int r = 0; r < 16; r++) {
            unsigned long long xp =
                *(const unsigned long long*)&Xs[(rbase + r) * K_IN + 2 * k2];
            asm("fma.rn.f32x2 %0, %1, %2, %0;" : "+l"(acc[r][0]) : "l"(xp), "l"(w0));
            asm("fma.rn.f32x2 %0, %1, %2, %0;" : "+l"(acc[r][1]) : "l"(xp), "l"(w1));
            asm("fma.rn.f32x2 %0, %1, %2, %0;" : "+l"(acc[r][2]) : "l"(xp), "l"(w2));
            asm("fma.rn.f32x2 %0, %1, %2, %0;" : "+l"(acc[r][3]) : "l"(xp), "l"(w3));
        }
    }

    float4 bv = *(const float4*)&b[cbase];
    #pragma unroll
    for (int r = 0; r < 16; r++) {
        int row = row0 + rbase + r;
        if (row < n) {
            float4 o;
            float lo, hi;
            asm("mov.b64 {%0,%1}, %2;" : "=f"(lo), "=f"(hi) : "l"(acc[r][0]));
            o.x = fmaxf(lo + hi + bv.x, 0.f);
            asm("mov.b64 {%0,%1}, %2;" : "=f"(lo), "=f"(hi) : "l"(acc[r][1]));
            o.y = fmaxf(lo + hi + bv.y, 0.f);
            asm("mov.b64 {%0,%1}, %2;" : "=f"(lo), "=f"(hi) : "l"(acc[r][2]));
            o.z = fmaxf(lo + hi + bv.z, 0.f);
            asm("mov.b64 {%0,%1}, %2;" : "=f"(lo), "=f"(hi) : "l"(acc[r][3]));
            o.w = fmaxf(lo + hi + bv.w, 0.f);
            *(float4*)&out[(size_t)row * H_OUT + cbase] = o;
        }
    }
}

// ---------------------------------------------------------------------------
extern "C" void kernel_launch(void* const* d_in, const int* in_sizes, int n_in,
                              void* d_out, int out_size) {
    const float* x  = (const float*)d_in[0];
    const int*   ei = (const int*)d_in[1];
    const float* W  = (const float*)d_in[2];
    const float* b  = (const float*)d_in[3];
    float* out = (float*)d_out;

    int n = in_sizes[0] / K_IN;     // 100000
    int e = in_sizes[1] / 2;        // 3200000
    const int* src = ei;
    const int* dst = ei + e;

    int nb_n = (n + 255) / 256;
    int nb_e = (e + 255) / 256;
    int nb_s = (n + SCAN_B - 1) / SCAN_B;   // 391

    zero_kernel<<<nb_n, 256>>>(n);
    count_kernel<<<nb_e, 256>>>(dst, e);
    dinv_kernel<<<nb_n, 256>>>(n);
    scanA_kernel<<<nb_s, SCAN_B>>>(n);
    scanB_kernel<<<1, 512>>>(nb_s);
    scanC_kernel<<<nb_s, SCAN_B>>>(n);
    fill_kernel<<<nb_e, 256>>>(src, dst, e);

    int nb_agg = (n * 32 + 255) / 256;
    agg_kernel<<<nb_agg, 256>>>(x, n);

    int smem = (K_IN * H_OUT + TILE_R * K_IN) * sizeof(float);  // 148480 B
    cudaFuncSetAttribute(gemm_kernel, cudaFuncAttributeMaxDynamicSharedMemorySize, smem);
    int nb_gemm = (n + TILE_R - 1) / TILE_R;
    gemm_kernel<<<nb_gemm, 256, smem>>>(W, b, out, n);
}